// round 2
// baseline (speedup 1.0000x reference)
#include <cuda_runtime.h>
#include <math.h>

#define H 1024
#define M 3584
#define E 8
#define T 2048
#define TOPK 2
#define A_MAX (T * TOPK)   // 4096 assignments

#define BT 64
#define BM 64
#define BK 16

// ---------------- scratch (device globals; no allocation allowed) ----------
__device__ int   g_expert_count[E];
__device__ int   g_expert_offset[E];
__device__ int   g_assign_token[A_MAX];
__device__ float g_assign_w[A_MAX];
__device__ int   g_top_i[A_MAX];
__device__ float g_top_w[A_MAX];
__device__ float g_hidden[(size_t)A_MAX * M];   // 4096 x 3584 fp32 (~224 MB)

// ---------------- zero output --------------------------------------------
__global__ void zero_kernel(float* __restrict__ out, int n) {
    int i = blockIdx.x * blockDim.x + threadIdx.x;
    if (i < n) out[i] = 0.f;
}

// ---------------- router: logits + softmax + top2 -------------------------
__global__ void __launch_bounds__(128) router_kernel(
    const float* __restrict__ x, const float* __restrict__ gw,
    float* __restrict__ logits_out)
{
    const int t = blockIdx.x;
    const int tid = threadIdx.x;
    const float* xr = x + (size_t)t * H;

    float acc[E];
#pragma unroll
    for (int e = 0; e < E; e++) acc[e] = 0.f;

    for (int h = tid; h < H; h += 128) {
        float xv = xr[h];
        const float* g = gw + (size_t)h * E;
#pragma unroll
        for (int e = 0; e < E; e++) acc[e] += xv * g[e];
    }

    __shared__ float red[128][E];
#pragma unroll
    for (int e = 0; e < E; e++) red[tid][e] = acc[e];
    __syncthreads();

    for (int s = 64; s > 0; s >>= 1) {
        if (tid < s) {
#pragma unroll
            for (int e = 0; e < E; e++) red[tid][e] += red[tid + s][e];
        }
        __syncthreads();
    }

    if (tid == 0) {
        float l[E];
#pragma unroll
        for (int e = 0; e < E; e++) {
            l[e] = red[0][e];
            if (logits_out) logits_out[(size_t)t * E + e] = l[e];
        }
        float mx = l[0];
#pragma unroll
        for (int e = 1; e < E; e++) mx = fmaxf(mx, l[e]);
        float p[E];
#pragma unroll
        for (int e = 0; e < E; e++) p[e] = expf(l[e] - mx);
        // argmax and second argmax of probs (== of logits); ties -> lowest idx
        int i0 = 0;
#pragma unroll
        for (int e = 1; e < E; e++) if (p[e] > p[i0]) i0 = e;
        int i1 = (i0 == 0) ? 1 : 0;
#pragma unroll
        for (int e = 0; e < E; e++) if (e != i0 && p[e] > p[i1]) i1 = e;
        float s2 = p[i0] + p[i1];
        g_top_i[t * 2 + 0] = i0; g_top_w[t * 2 + 0] = p[i0] / s2;
        g_top_i[t * 2 + 1] = i1; g_top_w[t * 2 + 1] = p[i1] / s2;
    }
}

// ---------------- group assignments by expert -----------------------------
__global__ void __launch_bounds__(256) build_assign_kernel() {
    __shared__ int cnt[E], cur[E];
    const int tid = threadIdx.x;
    if (tid < E) cnt[tid] = 0;
    __syncthreads();
    for (int a = tid; a < A_MAX; a += 256)
        atomicAdd(&cnt[g_top_i[a]], 1);
    __syncthreads();
    if (tid == 0) {
        int o = 0;
        for (int e = 0; e < E; e++) {
            g_expert_count[e] = cnt[e];
            g_expert_offset[e] = o;
            cur[e] = o;
            o += cnt[e];
        }
    }
    __syncthreads();
    for (int a = tid; a < A_MAX; a += 256) {
        int e = g_top_i[a];
        int pos = atomicAdd(&cur[e], 1);
        g_assign_token[pos] = a >> 1;       // token id
        g_assign_w[pos]     = g_top_w[a];
    }
}

// ---------------- GEMM1: hidden = silu(X*Wg) * (X*Wu) --------------------
__global__ void __launch_bounds__(256) gemm1_kernel(
    const float* __restrict__ x,
    const float* __restrict__ w_gate,
    const float* __restrict__ w_up)
{
    const int e   = blockIdx.z;
    const int cnt = g_expert_count[e];
    const int t0  = blockIdx.y * BT;
    if (t0 >= cnt) return;
    const int off = g_expert_offset[e];
    const int m0  = blockIdx.x * BM;

    __shared__ __align__(16) float As[BK][BT + 4];
    __shared__ __align__(16) float Bg[BK][BM];
    __shared__ __align__(16) float Bu[BK][BM];
    __shared__ int srow[BT];

    const int tid = threadIdx.x;
    if (tid < BT) {
        int r = t0 + tid;
        srow[tid] = (r < cnt) ? g_assign_token[off + r] : -1;
    }
    __syncthreads();

    const int tx = tid & 15, ty = tid >> 4;
    float accG[4][4] = {}, accU[4][4] = {};
    const float* Wg = w_gate + (size_t)e * H * M;
    const float* Wu = w_up   + (size_t)e * H * M;

    for (int k0 = 0; k0 < H; k0 += BK) {
#pragma unroll
        for (int i = 0; i < 4; i++) {
            int idx = tid + i * 256;           // 0..1023
            int tt = idx >> 4, kk = idx & 15;
            int row = srow[tt];
            As[kk][tt] = (row >= 0) ? x[(size_t)row * H + (k0 + kk)] : 0.f;
        }
#pragma unroll
        for (int i = 0; i < 4; i++) {
            int idx = tid + i * 256;
            int kk = idx >> 6, mm = idx & 63;
            size_t go = (size_t)(k0 + kk) * M + (m0 + mm);
            Bg[kk][mm] = Wg[go];
            Bu[kk][mm] = Wu[go];
        }
        __syncthreads();

#pragma unroll
        for (int k = 0; k < BK; k++) {
            float4 a4 = *reinterpret_cast<const float4*>(&As[k][ty * 4]);
            float4 g4 = *reinterpret_cast<const float4*>(&Bg[k][tx * 4]);
            float4 u4 = *reinterpret_cast<const float4*>(&Bu[k][tx * 4]);
            float a[4]  = {a4.x, a4.y, a4.z, a4.w};
            float bg[4] = {g4.x, g4.y, g4.z, g4.w};
            float bu[4] = {u4.x, u4.y, u4.z, u4.w};
#pragma unroll
            for (int i2 = 0; i2 < 4; i2++)
#pragma unroll
                for (int j = 0; j < 4; j++) {
                    accG[i2][j] += a[i2] * bg[j];
                    accU[i2][j] += a[i2] * bu[j];
                }
        }
        __syncthreads();
    }

#pragma unroll
    for (int i2 = 0; i2 < 4; i2++) {
        int lt = ty * 4 + i2;
        if (t0 + lt >= cnt) continue;
        size_t arow = (size_t)(off + t0 + lt) * M;
#pragma unroll
        for (int j = 0; j < 4; j++) {
            int m = m0 + tx * 4 + j;
            float g = accG[i2][j];
            float s = 1.f / (1.f + __expf(-g));
            g_hidden[arow + m] = (g * s) * accU[i2][j];
        }
    }
}

// ---------------- GEMM2: out += w * (hidden * Wd) -------------------------
__global__ void __launch_bounds__(256) gemm2_kernel(
    const float* __restrict__ w_down, float* __restrict__ out)
{
    const int e   = blockIdx.z;
    const int cnt = g_expert_count[e];
    const int t0  = blockIdx.y * BT;
    if (t0 >= cnt) return;
    const int off = g_expert_offset[e];
    const int h0  = blockIdx.x * BM;

    __shared__ __align__(16) float As[BK][BT + 4];
    __shared__ __align__(16) float Bd[BK][BM];

    const int tid = threadIdx.x;
    const int tx = tid & 15, ty = tid >> 4;
    float acc[4][4] = {};
    const float* Wd = w_down + (size_t)e * M * H;

    for (int k0 = 0; k0 < M; k0 += BK) {
#pragma unroll
        for (int i = 0; i < 4; i++) {
            int idx = tid + i * 256;
            int tt = idx >> 4, kk = idx & 15;
            int r = t0 + tt;
            As[kk][tt] = (r < cnt) ? g_hidden[(size_t)(off + r) * M + (k0 + kk)] : 0.f;
        }
#pragma unroll
        for (int i = 0; i < 4; i++) {
            int idx = tid + i * 256;
            int kk = idx >> 6, hh = idx & 63;
            Bd[kk][hh] = Wd[(size_t)(k0 + kk) * H + (h0 + hh)];
        }
        __syncthreads();

#pragma unroll
        for (int k = 0; k < BK; k++) {
            float4 a4 = *reinterpret_cast<const float4*>(&As[k][ty * 4]);
            float4 b4 = *reinterpret_cast<const float4*>(&Bd[k][tx * 4]);
            float a[4] = {a4.x, a4.y, a4.z, a4.w};
            float b[4] = {b4.x, b4.y, b4.z, b4.w};
#pragma unroll
            for (int i2 = 0; i2 < 4; i2++)
#pragma unroll
                for (int j = 0; j < 4; j++)
                    acc[i2][j] += a[i2] * b[j];
        }
        __syncthreads();
    }

#pragma unroll
    for (int i2 = 0; i2 < 4; i2++) {
        int lt = ty * 4 + i2;
        int r = t0 + lt;
        if (r >= cnt) continue;
        int a = off + r;
        int token = g_assign_token[a];
        float w = g_assign_w[a];
        float* orow = out + (size_t)token * H + h0 + tx * 4;
#pragma unroll
        for (int j = 0; j < 4; j++)
            atomicAdd(&orow[j], w * acc[i2][j]);
    }
}

// ---------------- launch ---------------------------------------------------
extern "C" void kernel_launch(void* const* d_in, const int* in_sizes, int n_in,
                              void* d_out, int out_size) {
    const float* hs     = (const float*)d_in[0];   // [2,1024,1024]
    const float* gate_w = (const float*)d_in[1];   // [1024,8]
    const float* w_gate = (const float*)d_in[2];   // [8,1024,3584]
    const float* w_up   = (const float*)d_in[3];   // [8,1024,3584]
    const float* w_down = (const float*)d_in[4];   // [8,3584,1024]
    float* out = (float*)d_out;

    // outputs: [out (T*H)] then [router_logits (T*E)] if present
    float* logits_out = (out_size >= T * H + T * E) ? (out + (size_t)T * H) : nullptr;

    // 1. zero whole output (it is poisoned; GEMM2 accumulates via atomicAdd)
    zero_kernel<<<(out_size + 255) / 256, 256>>>(out, out_size);

    // 2. router
    router_kernel<<<T, 128>>>(hs, gate_w, logits_out);

    // 3. group assignments by expert
    build_assign_kernel<<<1, 256>>>();

    // 4. GEMM1 (gate & up fused, silu epilogue)
    dim3 g1(M / BM, T / BT, E);   // 56 x 32 x 8
    gemm1_kernel<<<g1, 256>>>(hs, w_gate, w_up);

    // 5. GEMM2 (down, weighted scatter-add)
    dim3 g2(H / BM, T / BT, E);   // 16 x 32 x 8
    gemm2_kernel<<<g2, 256>>>(w_down, out);
}

// round 5
// speedup vs baseline: 2.8965x; 2.8965x over previous
#include <cuda_runtime.h>
#include <cuda_bf16.h>
#include <math.h>
#include <stdint.h>

#define H 1024
#define M 3584
#define E 8
#define T 2048
#define A_MAX (T * 2)
#define A_PAD (A_MAX + 128)

// ---------------------------------------------------------------------------
// scratch (device globals; allocation forbidden). Separate bf16 hi/lo planes,
// all K-contiguous for the GEMM that consumes them.
// ---------------------------------------------------------------------------
__device__ int   g_expert_count[E];
__device__ int   g_expert_offset[E];
__device__ int   g_assign_token[A_MAX];
__device__ float g_assign_w[A_MAX];
__device__ int   g_top_i[A_MAX];
__device__ float g_top_w[A_MAX];

__device__ __align__(16) __nv_bfloat16 g_x_hi[(size_t)T * H];
__device__ __align__(16) __nv_bfloat16 g_x_lo[(size_t)T * H];
__device__ __align__(16) __nv_bfloat16 g_wgT_hi[(size_t)E * M * H];  // [e][m][h]
__device__ __align__(16) __nv_bfloat16 g_wgT_lo[(size_t)E * M * H];
__device__ __align__(16) __nv_bfloat16 g_wuT_hi[(size_t)E * M * H];
__device__ __align__(16) __nv_bfloat16 g_wuT_lo[(size_t)E * M * H];
__device__ __align__(16) __nv_bfloat16 g_wdT_hi[(size_t)E * H * M];  // [e][h][m]
__device__ __align__(16) __nv_bfloat16 g_wdT_lo[(size_t)E * H * M];
__device__ __align__(16) __nv_bfloat16 g_hid_hi[(size_t)A_PAD * M];  // [assign][m]
__device__ __align__(16) __nv_bfloat16 g_hid_lo[(size_t)A_PAD * M];

// ---------------------------------------------------------------------------
// helpers
// ---------------------------------------------------------------------------
__device__ __forceinline__ uint32_t smem_u32(const void* p) {
    uint32_t a;
    asm("{ .reg .u64 t; cvta.to.shared.u64 t, %1; cvt.u32.u64 %0, t; }" : "=r"(a) : "l"(p));
    return a;
}
#define SWZ(x) ((x) ^ (((x) >> 3) & 0x70))

__device__ __forceinline__ void st128s(uint32_t addr, uint4 v) {
    asm volatile("st.shared.v4.b32 [%0], {%1,%2,%3,%4};"
                 :: "r"(addr), "r"(v.x), "r"(v.y), "r"(v.z), "r"(v.w) : "memory");
}

#define LDSM4(r, addr) \
    asm volatile("ldmatrix.sync.aligned.m8n8.x4.shared.b16 {%0,%1,%2,%3}, [%4];" \
        : "=r"((r)[0]), "=r"((r)[1]), "=r"((r)[2]), "=r"((r)[3]) : "r"(addr))
#define LDSM2(r, addr) \
    asm volatile("ldmatrix.sync.aligned.m8n8.x2.shared.b16 {%0,%1}, [%2];" \
        : "=r"((r)[0]), "=r"((r)[1]) : "r"(addr))

#define MMA16816(c, a, b) \
    asm volatile("mma.sync.aligned.m16n8k16.row.col.f32.bf16.bf16.f32 " \
        "{%0,%1,%2,%3}, {%4,%5,%6,%7}, {%8,%9}, {%0,%1,%2,%3};" \
        : "+f"((c)[0]), "+f"((c)[1]), "+f"((c)[2]), "+f"((c)[3]) \
        : "r"((a)[0]), "r"((a)[1]), "r"((a)[2]), "r"((a)[3]), "r"((b)[0]), "r"((b)[1]))

__device__ __forceinline__ void split2(float v0, float v1, uint32_t& hi, uint32_t& lo) {
    __nv_bfloat16 h0 = __float2bfloat16(v0);
    __nv_bfloat16 h1 = __float2bfloat16(v1);
    __nv_bfloat16 l0 = __float2bfloat16(v0 - __bfloat162float(h0));
    __nv_bfloat16 l1 = __float2bfloat16(v1 - __bfloat162float(h1));
    hi = (uint32_t)__bfloat16_as_ushort(h0) | ((uint32_t)__bfloat16_as_ushort(h1) << 16);
    lo = (uint32_t)__bfloat16_as_ushort(l0) | ((uint32_t)__bfloat16_as_ushort(l1) << 16);
}

// ---------------------------------------------------------------------------
// mma core: one 64-wide K chunk, warp tile 64 rows x 32 cols, 3-term emulation
// smem operand planes: [rows][64 bf16] per row 128B, SW128 swizzled
// ---------------------------------------------------------------------------
__device__ __forceinline__ void mma_chunk(float acc[4][4][4],
                                          uint32_t aHi, uint32_t aLo,
                                          uint32_t bHi, uint32_t bLo,
                                          int m0w, int n0w, int lane)
{
    const int lr = lane & 15;
    const int lc = (lane >> 4) << 3;
    const int bi = lane & 7;
    const int bk = ((lane >> 3) & 1) << 3;
#pragma unroll
    for (int ks = 0; ks < 4; ks++) {
        const int k0 = ks * 16;
        uint32_t bh[4][2], bl[4][2];
#pragma unroll
        for (int nf = 0; nf < 4; nf++) {
            uint32_t boff = SWZ((uint32_t)((n0w + nf * 8 + bi) * 128 + (k0 + bk) * 2));
            LDSM2(bh[nf], bHi + boff);
            LDSM2(bl[nf], bLo + boff);
        }
#pragma unroll
        for (int mf = 0; mf < 4; mf++) {
            uint32_t aoff = SWZ((uint32_t)((m0w + mf * 16 + lr) * 128 + (k0 + lc) * 2));
            uint32_t ah[4], al[4];
            LDSM4(ah, aHi + aoff);
            LDSM4(al, aLo + aoff);
#pragma unroll
            for (int nf = 0; nf < 4; nf++) {
                MMA16816(acc[mf][nf], ah, bh[nf]);
                MMA16816(acc[mf][nf], ah, bl[nf]);
                MMA16816(acc[mf][nf], al, bh[nf]);
            }
        }
    }
}

// ---------------------------------------------------------------------------
// small kernels
// ---------------------------------------------------------------------------
__global__ void zero_kernel(float* __restrict__ out, int n) {
    int i = blockIdx.x * blockDim.x + threadIdx.x;
    if (i < n) out[i] = 0.f;
}

__global__ void xconv_kernel(const float* __restrict__ x) {
    int i = blockIdx.x * blockDim.x + threadIdx.x;   // pair index
    if (i < T * H / 2) {
        uint32_t hi, lo;
        split2(x[2 * i], x[2 * i + 1], hi, lo);
        *(uint32_t*)(g_x_hi + 2 * i) = hi;
        *(uint32_t*)(g_x_lo + 2 * i) = lo;
    }
}

// transpose+split: in [e][R][C] fp32 -> plane [e][C][R] bf16 (K=R contiguous)
// which: 0 = w_gate, 1 = w_up (R=H,C=M);  2 = w_down (R=M,C=H)
// NOTE: output arrays are selected in DEVICE code (taking the address of a
// __device__ global from host code is UB — that was the R4 all-zeros bug).
__global__ void __launch_bounds__(256) trans_kernel(const float* __restrict__ in,
                                                    int which) {
    const int R = (which == 2) ? M : H;
    const int C = (which == 2) ? H : M;
    __nv_bfloat16* out_hi = (which == 0) ? g_wgT_hi : (which == 1) ? g_wuT_hi : g_wdT_hi;
    __nv_bfloat16* out_lo = (which == 0) ? g_wgT_lo : (which == 1) ? g_wuT_lo : g_wdT_lo;

    const int e = blockIdx.z;
    in     += (size_t)e * R * C;
    out_hi += (size_t)e * R * C;
    out_lo += (size_t)e * R * C;
    const int k0 = blockIdx.x * 64;
    const int n0 = blockIdx.y * 32;
    __shared__ float sm[64][33];
    const int tx = threadIdx.x, ty = threadIdx.y;
#pragma unroll
    for (int i = 0; i < 8; i++)
        sm[ty + i * 8][tx] = in[(size_t)(k0 + ty + i * 8) * C + n0 + tx];
    __syncthreads();
#pragma unroll
    for (int i = 0; i < 4; i++) {
        int n = i * 8 + ty;
        size_t base = (size_t)(n0 + n) * R + k0;
        uint32_t hi, lo;
        split2(sm[2 * tx][n], sm[2 * tx + 1][n], hi, lo);
        *(uint32_t*)(out_hi + base + 2 * tx) = hi;
        *(uint32_t*)(out_lo + base + 2 * tx) = lo;
    }
}

// ---------------------------------------------------------------------------
// router + grouping (validated in R2)
// ---------------------------------------------------------------------------
__global__ void __launch_bounds__(128) router_kernel(
    const float* __restrict__ x, const float* __restrict__ gw,
    float* __restrict__ logits_out)
{
    const int t = blockIdx.x;
    const int tid = threadIdx.x;
    const float* xr = x + (size_t)t * H;
    float acc[E];
#pragma unroll
    for (int e = 0; e < E; e++) acc[e] = 0.f;
    for (int h = tid; h < H; h += 128) {
        float xv = xr[h];
        const float* g = gw + (size_t)h * E;
#pragma unroll
        for (int e = 0; e < E; e++) acc[e] += xv * g[e];
    }
    __shared__ float red[128][E];
#pragma unroll
    for (int e = 0; e < E; e++) red[tid][e] = acc[e];
    __syncthreads();
    for (int s = 64; s > 0; s >>= 1) {
        if (tid < s)
#pragma unroll
            for (int e = 0; e < E; e++) red[tid][e] += red[tid + s][e];
        __syncthreads();
    }
    if (tid == 0) {
        float l[E];
#pragma unroll
        for (int e = 0; e < E; e++) {
            l[e] = red[0][e];
            if (logits_out) logits_out[(size_t)t * E + e] = l[e];
        }
        float mx = l[0];
#pragma unroll
        for (int e = 1; e < E; e++) mx = fmaxf(mx, l[e]);
        float p[E];
#pragma unroll
        for (int e = 0; e < E; e++) p[e] = expf(l[e] - mx);
        int i0 = 0;
#pragma unroll
        for (int e = 1; e < E; e++) if (p[e] > p[i0]) i0 = e;
        int i1 = (i0 == 0) ? 1 : 0;
#pragma unroll
        for (int e = 0; e < E; e++) if (e != i0 && p[e] > p[i1]) i1 = e;
        float s2 = p[i0] + p[i1];
        g_top_i[t * 2 + 0] = i0; g_top_w[t * 2 + 0] = p[i0] / s2;
        g_top_i[t * 2 + 1] = i1; g_top_w[t * 2 + 1] = p[i1] / s2;
    }
}

__global__ void __launch_bounds__(256) build_assign_kernel() {
    __shared__ int cnt[E], cur[E];
    const int tid = threadIdx.x;
    if (tid < E) cnt[tid] = 0;
    __syncthreads();
    for (int a = tid; a < A_MAX; a += 256) atomicAdd(&cnt[g_top_i[a]], 1);
    __syncthreads();
    if (tid == 0) {
        int o = 0;
        for (int e = 0; e < E; e++) {
            g_expert_count[e] = cnt[e];
            g_expert_offset[e] = o;
            cur[e] = o;
            o += cnt[e];
        }
    }
    __syncthreads();
    for (int a = tid; a < A_MAX; a += 256) {
        int e = g_top_i[a];
        int pos = atomicAdd(&cur[e], 1);
        g_assign_token[pos] = a >> 1;
        g_assign_w[pos]     = g_top_w[a];
    }
}

// ---------------------------------------------------------------------------
// GEMM1: hidden = silu(X*Wg) * (X*Wu)
// block: 128 gathered rows x 64 cols; warps 0-3 gate, 4-7 up (64x32 tiles)
// ---------------------------------------------------------------------------
#define G1_AHI 0
#define G1_ALO (16 * 1024)
#define G1_BGH (32 * 1024)
#define G1_BGL (40 * 1024)
#define G1_BUH (48 * 1024)
#define G1_BUL (56 * 1024)
#define G1_SROW (64 * 1024)
#define G1_SMEM (64 * 1024 + 512)

__global__ void __launch_bounds__(256, 2) gemm1_mma() {
    const int e   = blockIdx.z;
    const int cnt = g_expert_count[e];
    const int t0  = blockIdx.x * 128;
    if (t0 >= cnt) return;
    const int off = g_expert_offset[e];
    const int n0  = blockIdx.y * 64;

    extern __shared__ __align__(1024) char smem[];
    const uint32_t sb = smem_u32(smem);
    int* srow = (int*)(smem + G1_SROW);
    const int tid = threadIdx.x, wid = tid >> 5, lane = tid & 31;

    if (tid < 128)
        srow[tid] = (t0 + tid < cnt) ? g_assign_token[off + t0 + tid] : -1;
    __syncthreads();

    const int gwp    = wid & 3;
    const int warp_m = gwp >> 1, warp_n = gwp & 1;
    const bool isUp  = wid >= 4;

    float acc[4][4][4];
#pragma unroll
    for (int a = 0; a < 4; a++)
#pragma unroll
        for (int b = 0; b < 4; b++)
#pragma unroll
            for (int c = 0; c < 4; c++) acc[a][b][c] = 0.f;

    const uint32_t bHi = isUp ? sb + G1_BUH : sb + G1_BGH;
    const uint32_t bLo = isUp ? sb + G1_BUL : sb + G1_BGL;

    for (int ch = 0; ch < H / 64; ch++) {
        const int kg = ch * 64;
        // A planes (gathered): 128 rows x 128B, 8 threads/row
#pragma unroll
        for (int it = 0; it < 4; it++) {
            int idx = tid + it * 256;
            int r = idx >> 3, q = idx & 7;
            int tok = srow[r];
            uint4 vh = make_uint4(0, 0, 0, 0), vl = make_uint4(0, 0, 0, 0);
            if (tok >= 0) {
                vh = *(const uint4*)(g_x_hi + (size_t)tok * H + kg + q * 8);
                vl = *(const uint4*)(g_x_lo + (size_t)tok * H + kg + q * 8);
            }
            uint32_t o = SWZ((uint32_t)(r * 128 + q * 16));
            st128s(sb + G1_AHI + o, vh);
            st128s(sb + G1_ALO + o, vl);
        }
        // B gate / up planes: 64 rows each
#pragma unroll
        for (int it = 0; it < 2; it++) {
            int idx = tid + it * 256;
            int r = idx >> 3, q = idx & 7;
            size_t go = ((size_t)e * M + n0 + r) * H + kg + q * 8;
            uint32_t o = SWZ((uint32_t)(r * 128 + q * 16));
            st128s(sb + G1_BGH + o, *(const uint4*)(g_wgT_hi + go));
            st128s(sb + G1_BGL + o, *(const uint4*)(g_wgT_lo + go));
            st128s(sb + G1_BUH + o, *(const uint4*)(g_wuT_hi + go));
            st128s(sb + G1_BUL + o, *(const uint4*)(g_wuT_lo + go));
        }
        __syncthreads();
        mma_chunk(acc, sb + G1_AHI, sb + G1_ALO, bHi, bLo, warp_m * 64, warp_n * 32, lane);
        __syncthreads();
    }

    // epilogue: exchange up accums via smem, gate warps compute + store
    float* smemU = (float*)smem;   // [128][65] fp32 overlay (33 KB < 64 KB)
    if (isUp) {
#pragma unroll
        for (int mf = 0; mf < 4; mf++)
#pragma unroll
            for (int nf = 0; nf < 4; nf++)
#pragma unroll
                for (int i = 0; i < 4; i++) {
                    int r = warp_m * 64 + mf * 16 + (lane >> 2) + ((i >> 1) << 3);
                    int c = warp_n * 32 + nf * 8 + 2 * (lane & 3) + (i & 1);
                    smemU[r * 65 + c] = acc[mf][nf][i];
                }
    }
    __syncthreads();
    if (!isUp) {
#pragma unroll
        for (int mf = 0; mf < 4; mf++)
#pragma unroll
            for (int nf = 0; nf < 4; nf++) {
                int rb = warp_m * 64 + mf * 16 + (lane >> 2);
                int cb = warp_n * 32 + nf * 8 + 2 * (lane & 3);
#pragma unroll
                for (int hf = 0; hf < 2; hf++) {
                    int r = rb + hf * 8;
                    if (t0 + r < cnt) {
                        float g0 = acc[mf][nf][hf * 2 + 0];
                        float g1 = acc[mf][nf][hf * 2 + 1];
                        float u0 = smemU[r * 65 + cb];
                        float u1 = smemU[r * 65 + cb + 1];
                        float h0 = (g0 / (1.f + __expf(-g0))) * u0;
                        float h1 = (g1 / (1.f + __expf(-g1))) * u1;
                        uint32_t hi, lo;
                        split2(h0, h1, hi, lo);
                        size_t o = (size_t)(off + t0 + r) * M + n0 + cb;
                        *(uint32_t*)(g_hid_hi + o) = hi;
                        *(uint32_t*)(g_hid_lo + o) = lo;
                    }
                }
            }
    }
}

// ---------------------------------------------------------------------------
// GEMM2: out += w * (hidden * WdT)
// block: 128 rows x 128 H-cols; 8 warps (2m x 4n, 64x32 tiles); K = M
// ---------------------------------------------------------------------------
#define G2_AHI 0
#define G2_ALO (16 * 1024)
#define G2_BDH (32 * 1024)
#define G2_BDL (48 * 1024)
#define G2_SMEM (64 * 1024)

__global__ void __launch_bounds__(256, 2) gemm2_mma(float* __restrict__ out) {
    const int e   = blockIdx.z;
    const int cnt = g_expert_count[e];
    const int t0  = blockIdx.x * 128;
    if (t0 >= cnt) return;
    const int off = g_expert_offset[e];
    const int h0  = blockIdx.y * 128;

    extern __shared__ __align__(1024) char smem[];
    const uint32_t sb = smem_u32(smem);
    const int tid = threadIdx.x, wid = tid >> 5, lane = tid & 31;
    const int warp_m = wid >> 2, warp_n = wid & 3;

    float acc[4][4][4];
#pragma unroll
    for (int a = 0; a < 4; a++)
#pragma unroll
        for (int b = 0; b < 4; b++)
#pragma unroll
            for (int c = 0; c < 4; c++) acc[a][b][c] = 0.f;

    for (int ch = 0; ch < M / 64; ch++) {
        const int kg = ch * 64;
        // A: hidden rows (contiguous group)
#pragma unroll
        for (int it = 0; it < 4; it++) {
            int idx = tid + it * 256;
            int r = idx >> 3, q = idx & 7;
            size_t go = (size_t)(off + t0 + r) * M + kg + q * 8;
            uint32_t o = SWZ((uint32_t)(r * 128 + q * 16));
            st128s(sb + G2_AHI + o, *(const uint4*)(g_hid_hi + go));
            st128s(sb + G2_ALO + o, *(const uint4*)(g_hid_lo + go));
        }
        // B: down weights, 128 rows
#pragma unroll
        for (int it = 0; it < 4; it++) {
            int idx = tid + it * 256;
            int r = idx >> 3, q = idx & 7;
            size_t go = ((size_t)e * H + h0 + r) * M + kg + q * 8;
            uint32_t o = SWZ((uint32_t)(r * 128 + q * 16));
            st128s(sb + G2_BDH + o, *(const uint4*)(g_wdT_hi + go));
            st128s(sb + G2_BDL + o, *(const uint4*)(g_wdT_lo + go));
        }
        __syncthreads();
        mma_chunk(acc, sb + G2_AHI, sb + G2_ALO, sb + G2_BDH, sb + G2_BDL,
                  warp_m * 64, warp_n * 32, lane);
        __syncthreads();
    }

    // epilogue: weighted atomic scatter-add
#pragma unroll
    for (int mf = 0; mf < 4; mf++) {
        int rb = warp_m * 64 + mf * 16 + (lane >> 2);
#pragma unroll
        for (int hf = 0; hf < 2; hf++) {
            int r = rb + hf * 8;
            if (t0 + r < cnt) {
                int a = off + t0 + r;
                int tok = g_assign_token[a];
                float w = g_assign_w[a];
                float* orow = out + (size_t)tok * H + h0;
#pragma unroll
                for (int nf = 0; nf < 4; nf++) {
                    int c = warp_n * 32 + nf * 8 + 2 * (lane & 3);
                    atomicAdd(&orow[c],     w * acc[mf][nf][hf * 2 + 0]);
                    atomicAdd(&orow[c + 1], w * acc[mf][nf][hf * 2 + 1]);
                }
            }
        }
    }
}

// ---------------------------------------------------------------------------
// launch
// ---------------------------------------------------------------------------
extern "C" void kernel_launch(void* const* d_in, const int* in_sizes, int n_in,
                              void* d_out, int out_size) {
    const float* hs     = (const float*)d_in[0];
    const float* gate_w = (const float*)d_in[1];
    const float* w_gate = (const float*)d_in[2];
    const float* w_up   = (const float*)d_in[3];
    const float* w_down = (const float*)d_in[4];
    float* out = (float*)d_out;
    float* logits_out = (out_size >= T * H + T * E) ? (out + (size_t)T * H) : nullptr;

    cudaFuncSetAttribute(gemm1_mma, cudaFuncAttributeMaxDynamicSharedMemorySize, G1_SMEM);
    cudaFuncSetAttribute(gemm2_mma, cudaFuncAttributeMaxDynamicSharedMemorySize, G2_SMEM);

    zero_kernel<<<(out_size + 255) / 256, 256>>>(out, out_size);
    xconv_kernel<<<(T * H / 2 + 255) / 256, 256>>>(hs);

    dim3 tb(32, 8);
    trans_kernel<<<dim3(H / 64, M / 32, E), tb>>>(w_gate, 0);
    trans_kernel<<<dim3(H / 64, M / 32, E), tb>>>(w_up,   1);
    trans_kernel<<<dim3(M / 64, H / 32, E), tb>>>(w_down, 2);

    router_kernel<<<T, 128>>>(hs, gate_w, logits_out);
    build_assign_kernel<<<1, 256>>>();

    gemm1_mma<<<dim3(A_MAX / 128, M / 64, E), 256, G1_SMEM>>>();
    gemm2_mma<<<dim3(A_MAX / 128, H / 128, E), 256, G2_SMEM>>>(out);
}

// round 6
// speedup vs baseline: 3.1630x; 1.0920x over previous
#include <cuda_runtime.h>
#include <cuda_bf16.h>
#include <math.h>
#include <stdint.h>

#define H 1024
#define M 3584
#define E 8
#define T 2048
#define A_MAX (T * 2)
#define A_PAD (A_MAX + 128)

// ---------------------------------------------------------------------------
// scratch (device globals; allocation forbidden)
// ---------------------------------------------------------------------------
__device__ int   g_expert_count[E];
__device__ int   g_expert_offset[E];
__device__ int   g_assign_token[A_MAX];
__device__ float g_assign_w[A_MAX];
__device__ int   g_top_i[A_MAX];
__device__ float g_top_w[A_MAX];

__device__ __align__(16) __nv_bfloat16 g_x_hi[(size_t)T * H];
__device__ __align__(16) __nv_bfloat16 g_x_lo[(size_t)T * H];
__device__ __align__(16) __nv_bfloat16 g_wgT_hi[(size_t)E * M * H];  // [e][m][h]
__device__ __align__(16) __nv_bfloat16 g_wgT_lo[(size_t)E * M * H];
__device__ __align__(16) __nv_bfloat16 g_wuT_hi[(size_t)E * M * H];
__device__ __align__(16) __nv_bfloat16 g_wuT_lo[(size_t)E * M * H];
__device__ __align__(16) __nv_bfloat16 g_wdT_hi[(size_t)E * H * M];  // [e][h][m]
__device__ __align__(16) __nv_bfloat16 g_wdT_lo[(size_t)E * H * M];
__device__ __align__(16) __nv_bfloat16 g_hid_hi[(size_t)A_PAD * M];  // [assign][m]
__device__ __align__(16) __nv_bfloat16 g_hid_lo[(size_t)A_PAD * M];

// ---------------------------------------------------------------------------
// helpers
// ---------------------------------------------------------------------------
__device__ __forceinline__ uint32_t smem_u32(const void* p) {
    uint32_t a;
    asm("{ .reg .u64 t; cvta.to.shared.u64 t, %1; cvt.u32.u64 %0, t; }" : "=r"(a) : "l"(p));
    return a;
}
#define SWZ(x) ((x) ^ (((x) >> 3) & 0x70))

#define CP16(dst, src) \
    asm volatile("cp.async.cg.shared.global [%0], [%1], 16;" \
                 :: "r"(dst), "l"(__cvta_generic_to_global(src)) : "memory")
#define CP16Z(dst, src, sz) \
    asm volatile("cp.async.cg.shared.global [%0], [%1], 16, %2;" \
                 :: "r"(dst), "l"(__cvta_generic_to_global(src)), "r"(sz) : "memory")
#define CP_COMMIT() asm volatile("cp.async.commit_group;" ::: "memory")
#define CP_WAIT(n)  asm volatile("cp.async.wait_group %0;" :: "n"(n) : "memory")

#define LDSM4(r, addr) \
    asm volatile("ldmatrix.sync.aligned.m8n8.x4.shared.b16 {%0,%1,%2,%3}, [%4];" \
        : "=r"((r)[0]), "=r"((r)[1]), "=r"((r)[2]), "=r"((r)[3]) : "r"(addr))
#define LDSM2(r, addr) \
    asm volatile("ldmatrix.sync.aligned.m8n8.x2.shared.b16 {%0,%1}, [%2];" \
        : "=r"((r)[0]), "=r"((r)[1]) : "r"(addr))

#define MMA16816(c, a, b) \
    asm volatile("mma.sync.aligned.m16n8k16.row.col.f32.bf16.bf16.f32 " \
        "{%0,%1,%2,%3}, {%4,%5,%6,%7}, {%8,%9}, {%0,%1,%2,%3};" \
        : "+f"((c)[0]), "+f"((c)[1]), "+f"((c)[2]), "+f"((c)[3]) \
        : "r"((a)[0]), "r"((a)[1]), "r"((a)[2]), "r"((a)[3]), "r"((b)[0]), "r"((b)[1]))

__device__ __forceinline__ void split2(float v0, float v1, uint32_t& hi, uint32_t& lo) {
    __nv_bfloat16 h0 = __float2bfloat16(v0);
    __nv_bfloat16 h1 = __float2bfloat16(v1);
    __nv_bfloat16 l0 = __float2bfloat16(v0 - __bfloat162float(h0));
    __nv_bfloat16 l1 = __float2bfloat16(v1 - __bfloat162float(h1));
    hi = (uint32_t)__bfloat16_as_ushort(h0) | ((uint32_t)__bfloat16_as_ushort(h1) << 16);
    lo = (uint32_t)__bfloat16_as_ushort(l0) | ((uint32_t)__bfloat16_as_ushort(l1) << 16);
}

// ---------------------------------------------------------------------------
// mma core: one 64-wide K chunk, warp tile 64 rows x 32 cols, 3-term emulation
// ---------------------------------------------------------------------------
__device__ __forceinline__ void mma_chunk(float acc[4][4][4],
                                          uint32_t aHi, uint32_t aLo,
                                          uint32_t bHi, uint32_t bLo,
                                          int m0w, int n0w, int lane)
{
    const int lr = lane & 15;
    const int lc = (lane >> 4) << 3;
    const int bi = lane & 7;
    const int bk = ((lane >> 3) & 1) << 3;
#pragma unroll
    for (int ks = 0; ks < 4; ks++) {
        const int k0 = ks * 16;
        uint32_t bh[4][2], bl[4][2];
#pragma unroll
        for (int nf = 0; nf < 4; nf++) {
            uint32_t boff = SWZ((uint32_t)((n0w + nf * 8 + bi) * 128 + (k0 + bk) * 2));
            LDSM2(bh[nf], bHi + boff);
            LDSM2(bl[nf], bLo + boff);
        }
#pragma unroll
        for (int mf = 0; mf < 4; mf++) {
            uint32_t aoff = SWZ((uint32_t)((m0w + mf * 16 + lr) * 128 + (k0 + lc) * 2));
            uint32_t ah[4], al[4];
            LDSM4(ah, aHi + aoff);
            LDSM4(al, aLo + aoff);
#pragma unroll
            for (int nf = 0; nf < 4; nf++) {
                MMA16816(acc[mf][nf], ah, bh[nf]);
                MMA16816(acc[mf][nf], ah, bl[nf]);
                MMA16816(acc[mf][nf], al, bh[nf]);
            }
        }
    }
}

// ---------------------------------------------------------------------------
// small kernels
// ---------------------------------------------------------------------------
__global__ void zero_kernel(float* __restrict__ out, int n) {
    int i = blockIdx.x * blockDim.x + threadIdx.x;
    if (i < n) out[i] = 0.f;
}

__global__ void xconv_kernel(const float* __restrict__ x) {
    int i = blockIdx.x * blockDim.x + threadIdx.x;
    if (i < T * H / 2) {
        uint32_t hi, lo;
        split2(x[2 * i], x[2 * i + 1], hi, lo);
        *(uint32_t*)(g_x_hi + 2 * i) = hi;
        *(uint32_t*)(g_x_lo + 2 * i) = lo;
    }
}

// transpose+split: in [e][R][C] fp32 -> plane [e][C][R] bf16 (K=R contiguous)
// which: 0 = w_gate, 1 = w_up (R=H,C=M);  2 = w_down (R=M,C=H)
// outputs selected in DEVICE code (host address-of __device__ global is UB).
__global__ void __launch_bounds__(256) trans_kernel(const float* __restrict__ in,
                                                    int which) {
    const int R = (which == 2) ? M : H;
    const int C = (which == 2) ? H : M;
    __nv_bfloat16* out_hi = (which == 0) ? g_wgT_hi : (which == 1) ? g_wuT_hi : g_wdT_hi;
    __nv_bfloat16* out_lo = (which == 0) ? g_wgT_lo : (which == 1) ? g_wuT_lo : g_wdT_lo;

    const int e = blockIdx.z;
    in     += (size_t)e * R * C;
    out_hi += (size_t)e * R * C;
    out_lo += (size_t)e * R * C;
    const int k0 = blockIdx.x * 64;
    const int n0 = blockIdx.y * 32;
    __shared__ float sm[64][33];
    const int tx = threadIdx.x, ty = threadIdx.y;
#pragma unroll
    for (int i = 0; i < 8; i++)
        sm[ty + i * 8][tx] = in[(size_t)(k0 + ty + i * 8) * C + n0 + tx];
    __syncthreads();
#pragma unroll
    for (int i = 0; i < 4; i++) {
        int n = i * 8 + ty;
        size_t base = (size_t)(n0 + n) * R + k0;
        uint32_t hi, lo;
        split2(sm[2 * tx][n], sm[2 * tx + 1][n], hi, lo);
        *(uint32_t*)(out_hi + base + 2 * tx) = hi;
        *(uint32_t*)(out_lo + base + 2 * tx) = lo;
    }
}

// ---------------------------------------------------------------------------
// router + grouping (validated)
// ---------------------------------------------------------------------------
__global__ void __launch_bounds__(128) router_kernel(
    const float* __restrict__ x, const float* __restrict__ gw,
    float* __restrict__ logits_out)
{
    const int t = blockIdx.x;
    const int tid = threadIdx.x;
    const float* xr = x + (size_t)t * H;
    float acc[E];
#pragma unroll
    for (int e = 0; e < E; e++) acc[e] = 0.f;
    for (int h = tid; h < H; h += 128) {
        float xv = xr[h];
        const float* g = gw + (size_t)h * E;
#pragma unroll
        for (int e = 0; e < E; e++) acc[e] += xv * g[e];
    }
    __shared__ float red[128][E];
#pragma unroll
    for (int e = 0; e < E; e++) red[tid][e] = acc[e];
    __syncthreads();
    for (int s = 64; s > 0; s >>= 1) {
        if (tid < s)
#pragma unroll
            for (int e = 0; e < E; e++) red[tid][e] += red[tid + s][e];
        __syncthreads();
    }
    if (tid == 0) {
        float l[E];
#pragma unroll
        for (int e = 0; e < E; e++) {
            l[e] = red[0][e];
            if (logits_out) logits_out[(size_t)t * E + e] = l[e];
        }
        float mx = l[0];
#pragma unroll
        for (int e = 1; e < E; e++) mx = fmaxf(mx, l[e]);
        float p[E];
#pragma unroll
        for (int e = 0; e < E; e++) p[e] = expf(l[e] - mx);
        int i0 = 0;
#pragma unroll
        for (int e = 1; e < E; e++) if (p[e] > p[i0]) i0 = e;
        int i1 = (i0 == 0) ? 1 : 0;
#pragma unroll
        for (int e = 0; e < E; e++) if (e != i0 && p[e] > p[i1]) i1 = e;
        float s2 = p[i0] + p[i1];
        g_top_i[t * 2 + 0] = i0; g_top_w[t * 2 + 0] = p[i0] / s2;
        g_top_i[t * 2 + 1] = i1; g_top_w[t * 2 + 1] = p[i1] / s2;
    }
}

__global__ void __launch_bounds__(256) build_assign_kernel() {
    __shared__ int cnt[E], cur[E];
    const int tid = threadIdx.x;
    if (tid < E) cnt[tid] = 0;
    __syncthreads();
    for (int a = tid; a < A_MAX; a += 256) atomicAdd(&cnt[g_top_i[a]], 1);
    __syncthreads();
    if (tid == 0) {
        int o = 0;
        for (int e = 0; e < E; e++) {
            g_expert_count[e] = cnt[e];
            g_expert_offset[e] = o;
            cur[e] = o;
            o += cnt[e];
        }
    }
    __syncthreads();
    for (int a = tid; a < A_MAX; a += 256) {
        int e = g_top_i[a];
        int pos = atomicAdd(&cur[e], 1);
        g_assign_token[pos] = a >> 1;
        g_assign_w[pos]     = g_top_w[a];
    }
}

// ---------------------------------------------------------------------------
// GEMM1: hidden = silu(X*Wg) * (X*Wu)
// 128 gathered rows x 64 cols; warps 0-3 gate, 4-7 up; cp.async double-buffer
// stage (64KB): AHI 0 | ALO 16K | BGH 32K | BGL 40K | BUH 48K | BUL 56K
// ---------------------------------------------------------------------------
#define G1_STAGE 65536
#define G1_ALO 16384
#define G1_BGH 32768
#define G1_BGL 40960
#define G1_BUH 49152
#define G1_BUL 57344
#define G1_SROW (2 * G1_STAGE)
#define G1_SMEM (2 * G1_STAGE + 512)

__device__ __forceinline__ void g1_load(uint32_t stg, int e, int n0, int kg,
                                        const int* srow, int tid) {
#pragma unroll
    for (int it = 0; it < 4; it++) {
        int idx = tid + it * 256;
        int r = idx >> 3, q = idx & 7;
        int tok = srow[r];
        uint32_t sz = (tok >= 0) ? 16u : 0u;
        int tk = (tok >= 0) ? tok : 0;
        size_t go = (size_t)tk * H + kg + q * 8;
        uint32_t o = SWZ((uint32_t)(r * 128 + q * 16));
        CP16Z(stg + o,          g_x_hi + go, sz);
        CP16Z(stg + G1_ALO + o, g_x_lo + go, sz);
    }
#pragma unroll
    for (int it = 0; it < 2; it++) {
        int idx = tid + it * 256;
        int r = idx >> 3, q = idx & 7;
        size_t go = ((size_t)e * M + n0 + r) * H + kg + q * 8;
        uint32_t o = SWZ((uint32_t)(r * 128 + q * 16));
        CP16(stg + G1_BGH + o, g_wgT_hi + go);
        CP16(stg + G1_BGL + o, g_wgT_lo + go);
        CP16(stg + G1_BUH + o, g_wuT_hi + go);
        CP16(stg + G1_BUL + o, g_wuT_lo + go);
    }
}

__global__ void __launch_bounds__(256, 1) gemm1_mma() {
    const int e   = blockIdx.z;
    const int cnt = g_expert_count[e];
    const int t0  = blockIdx.x * 128;
    if (t0 >= cnt) return;
    const int off = g_expert_offset[e];
    const int n0  = blockIdx.y * 64;

    extern __shared__ __align__(1024) char smem[];
    const uint32_t sb = smem_u32(smem);
    int* srow = (int*)(smem + G1_SROW);
    const int tid = threadIdx.x, wid = tid >> 5, lane = tid & 31;

    if (tid < 128)
        srow[tid] = (t0 + tid < cnt) ? g_assign_token[off + t0 + tid] : -1;
    __syncthreads();

    const int gwp    = wid & 3;
    const int warp_m = gwp >> 1, warp_n = gwp & 1;
    const bool isUp  = wid >= 4;

    float acc[4][4][4];
#pragma unroll
    for (int a = 0; a < 4; a++)
#pragma unroll
        for (int b = 0; b < 4; b++)
#pragma unroll
            for (int c = 0; c < 4; c++) acc[a][b][c] = 0.f;

    const uint32_t bOffHi = isUp ? G1_BUH : G1_BGH;
    const uint32_t bOffLo = isUp ? G1_BUL : G1_BGL;

    const int NCH = H / 64;   // 16
    g1_load(sb, e, n0, 0, srow, tid);
    CP_COMMIT();
    for (int ch = 0; ch < NCH; ch++) {
        const uint32_t cur = sb + (uint32_t)(ch & 1) * G1_STAGE;
        if (ch + 1 < NCH) {
            g1_load(sb + (uint32_t)((ch + 1) & 1) * G1_STAGE, e, n0, (ch + 1) * 64, srow, tid);
            CP_COMMIT();
            CP_WAIT(1);
        } else {
            CP_WAIT(0);
        }
        __syncthreads();
        mma_chunk(acc, cur, cur + G1_ALO, cur + bOffHi, cur + bOffLo,
                  warp_m * 64, warp_n * 32, lane);
        __syncthreads();
    }

    // epilogue: exchange up accums via smem, gate warps compute + store
    float* smemU = (float*)smem;   // [128][65] fp32 overlay
    if (isUp) {
#pragma unroll
        for (int mf = 0; mf < 4; mf++)
#pragma unroll
            for (int nf = 0; nf < 4; nf++)
#pragma unroll
                for (int i = 0; i < 4; i++) {
                    int r = warp_m * 64 + mf * 16 + (lane >> 2) + ((i >> 1) << 3);
                    int c = warp_n * 32 + nf * 8 + 2 * (lane & 3) + (i & 1);
                    smemU[r * 65 + c] = acc[mf][nf][i];
                }
    }
    __syncthreads();
    if (!isUp) {
#pragma unroll
        for (int mf = 0; mf < 4; mf++)
#pragma unroll
            for (int nf = 0; nf < 4; nf++) {
                int rb = warp_m * 64 + mf * 16 + (lane >> 2);
                int cb = warp_n * 32 + nf * 8 + 2 * (lane & 3);
#pragma unroll
                for (int hf = 0; hf < 2; hf++) {
                    int r = rb + hf * 8;
                    if (t0 + r < cnt) {
                        float g0 = acc[mf][nf][hf * 2 + 0];
                        float g1 = acc[mf][nf][hf * 2 + 1];
                        float u0 = smemU[r * 65 + cb];
                        float u1 = smemU[r * 65 + cb + 1];
                        float h0 = (g0 / (1.f + __expf(-g0))) * u0;
                        float h1 = (g1 / (1.f + __expf(-g1))) * u1;
                        uint32_t hi, lo;
                        split2(h0, h1, hi, lo);
                        size_t o = (size_t)(off + t0 + r) * M + n0 + cb;
                        *(uint32_t*)(g_hid_hi + o) = hi;
                        *(uint32_t*)(g_hid_lo + o) = lo;
                    }
                }
            }
    }
}

// ---------------------------------------------------------------------------
// GEMM2: out += w * (hidden * WdT)
// 128 rows x 128 H-cols; 8 warps (2m x 4n); cp.async double-buffer
// stage (64KB): AHI 0 | ALO 16K | BDH 32K | BDL 48K
// ---------------------------------------------------------------------------
#define G2_STAGE 65536
#define G2_ALO 16384
#define G2_BDH 32768
#define G2_BDL 49152
#define G2_SMEM (2 * G2_STAGE)

__device__ __forceinline__ void g2_load(uint32_t stg, int e, int h0, int kg,
                                        int arow0, int tid) {
#pragma unroll
    for (int it = 0; it < 4; it++) {
        int idx = tid + it * 256;
        int r = idx >> 3, q = idx & 7;
        size_t go = (size_t)(arow0 + r) * M + kg + q * 8;
        uint32_t o = SWZ((uint32_t)(r * 128 + q * 16));
        CP16(stg + o,          g_hid_hi + go);
        CP16(stg + G2_ALO + o, g_hid_lo + go);
    }
#pragma unroll
    for (int it = 0; it < 4; it++) {
        int idx = tid + it * 256;
        int r = idx >> 3, q = idx & 7;
        size_t go = ((size_t)e * H + h0 + r) * M + kg + q * 8;
        uint32_t o = SWZ((uint32_t)(r * 128 + q * 16));
        CP16(stg + G2_BDH + o, g_wdT_hi + go);
        CP16(stg + G2_BDL + o, g_wdT_lo + go);
    }
}

__global__ void __launch_bounds__(256, 1) gemm2_mma(float* __restrict__ out) {
    const int e   = blockIdx.z;
    const int cnt = g_expert_count[e];
    const int t0  = blockIdx.x * 128;
    if (t0 >= cnt) return;
    const int off = g_expert_offset[e];
    const int h0  = blockIdx.y * 128;

    extern __shared__ __align__(1024) char smem[];
    const uint32_t sb = smem_u32(smem);
    const int tid = threadIdx.x, wid = tid >> 5, lane = tid & 31;
    const int warp_m = wid >> 2, warp_n = wid & 3;

    float acc[4][4][4];
#pragma unroll
    for (int a = 0; a < 4; a++)
#pragma unroll
        for (int b = 0; b < 4; b++)
#pragma unroll
            for (int c = 0; c < 4; c++) acc[a][b][c] = 0.f;

    const int NCH = M / 64;   // 56
    g2_load(sb, e, h0, 0, off + t0, tid);
    CP_COMMIT();
    for (int ch = 0; ch < NCH; ch++) {
        const uint32_t cur = sb + (uint32_t)(ch & 1) * G2_STAGE;
        if (ch + 1 < NCH) {
            g2_load(sb + (uint32_t)((ch + 1) & 1) * G2_STAGE, e, h0, (ch + 1) * 64, off + t0, tid);
            CP_COMMIT();
            CP_WAIT(1);
        } else {
            CP_WAIT(0);
        }
        __syncthreads();
        mma_chunk(acc, cur, cur + G2_ALO, cur + G2_BDH, cur + G2_BDL,
                  warp_m * 64, warp_n * 32, lane);
        __syncthreads();
    }

    // epilogue: weighted atomic scatter-add
#pragma unroll
    for (int mf = 0; mf < 4; mf++) {
        int rb = warp_m * 64 + mf * 16 + (lane >> 2);
#pragma unroll
        for (int hf = 0; hf < 2; hf++) {
            int r = rb + hf * 8;
            if (t0 + r < cnt) {
                int a = off + t0 + r;
                int tok = g_assign_token[a];
                float w = g_assign_w[a];
                float* orow = out + (size_t)tok * H + h0;
#pragma unroll
                for (int nf = 0; nf < 4; nf++) {
                    int c = warp_n * 32 + nf * 8 + 2 * (lane & 3);
                    atomicAdd(&orow[c],     w * acc[mf][nf][hf * 2 + 0]);
                    atomicAdd(&orow[c + 1], w * acc[mf][nf][hf * 2 + 1]);
                }
            }
        }
    }
}

// ---------------------------------------------------------------------------
// launch
// ---------------------------------------------------------------------------
extern "C" void kernel_launch(void* const* d_in, const int* in_sizes, int n_in,
                              void* d_out, int out_size) {
    const float* hs     = (const float*)d_in[0];
    const float* gate_w = (const float*)d_in[1];
    const float* w_gate = (const float*)d_in[2];
    const float* w_up   = (const float*)d_in[3];
    const float* w_down = (const float*)d_in[4];
    float* out = (float*)d_out;
    float* logits_out = (out_size >= T * H + T * E) ? (out + (size_t)T * H) : nullptr;

    cudaFuncSetAttribute(gemm1_mma, cudaFuncAttributeMaxDynamicSharedMemorySize, G1_SMEM);
    cudaFuncSetAttribute(gemm2_mma, cudaFuncAttributeMaxDynamicSharedMemorySize, G2_SMEM);

    zero_kernel<<<(out_size + 255) / 256, 256>>>(out, out_size);
    xconv_kernel<<<(T * H / 2 + 255) / 256, 256>>>(hs);

    dim3 tb(32, 8);
    trans_kernel<<<dim3(H / 64, M / 32, E), tb>>>(w_gate, 0);
    trans_kernel<<<dim3(H / 64, M / 32, E), tb>>>(w_up,   1);
    trans_kernel<<<dim3(M / 64, H / 32, E), tb>>>(w_down, 2);

    router_kernel<<<T, 128>>>(hs, gate_w, logits_out);
    build_assign_kernel<<<1, 256>>>();

    gemm1_mma<<<dim3(A_MAX / 128, M / 64, E), 256, G1_SMEM>>>();
    gemm2_mma<<<dim3(A_MAX / 128, H / 128, E), 256, G2_SMEM>>>(out);
}

// round 7
// speedup vs baseline: 6.9278x; 2.1903x over previous
#include <cuda_runtime.h>
#include <cuda_fp16.h>
#include <math.h>
#include <stdint.h>

#define H 1024
#define M 3584
#define E 8
#define T 2048
#define A_MAX (T * 2)
#define A_PAD (A_MAX + 128)

// ---------------------------------------------------------------------------
// scratch (device globals; allocation forbidden). Single fp16 planes, K-major.
// ---------------------------------------------------------------------------
__device__ int   g_expert_count[E];
__device__ int   g_expert_offset[E];
__device__ int   g_assign_token[A_MAX];
__device__ float g_assign_w[A_MAX];
__device__ int   g_top_i[A_MAX];
__device__ float g_top_w[A_MAX];

__device__ __align__(16) __half g_xh [(size_t)T * H];
__device__ __align__(16) __half g_wg [(size_t)E * M * H];   // [e][m][h]
__device__ __align__(16) __half g_wu [(size_t)E * M * H];   // [e][m][h]
__device__ __align__(16) __half g_wd [(size_t)E * H * M];   // [e][h][m]
__device__ __align__(16) __half g_hid[(size_t)A_PAD * M];   // [assign][m]

// ---------------------------------------------------------------------------
// helpers
// ---------------------------------------------------------------------------
__device__ __forceinline__ uint32_t smem_u32(const void* p) {
    uint32_t a;
    asm("{ .reg .u64 t; cvta.to.shared.u64 t, %1; cvt.u32.u64 %0, t; }" : "=r"(a) : "l"(p));
    return a;
}
#define SWZ(x) ((x) ^ (((x) >> 3) & 0x70))

#define CP16(dst, src) \
    asm volatile("cp.async.cg.shared.global [%0], [%1], 16;" \
                 :: "r"(dst), "l"(__cvta_generic_to_global(src)) : "memory")
#define CP16Z(dst, src, sz) \
    asm volatile("cp.async.cg.shared.global [%0], [%1], 16, %2;" \
                 :: "r"(dst), "l"(__cvta_generic_to_global(src)), "r"(sz) : "memory")
#define CP_COMMIT() asm volatile("cp.async.commit_group;" ::: "memory")
#define CP_WAIT(n)  asm volatile("cp.async.wait_group %0;" :: "n"(n) : "memory")

#define LDSM4(r, addr) \
    asm volatile("ldmatrix.sync.aligned.m8n8.x4.shared.b16 {%0,%1,%2,%3}, [%4];" \
        : "=r"((r)[0]), "=r"((r)[1]), "=r"((r)[2]), "=r"((r)[3]) : "r"(addr))
#define LDSM2(r, addr) \
    asm volatile("ldmatrix.sync.aligned.m8n8.x2.shared.b16 {%0,%1}, [%2];" \
        : "=r"((r)[0]), "=r"((r)[1]) : "r"(addr))

#define MMA16816(c, a, b) \
    asm volatile("mma.sync.aligned.m16n8k16.row.col.f32.f16.f16.f32 " \
        "{%0,%1,%2,%3}, {%4,%5,%6,%7}, {%8,%9}, {%0,%1,%2,%3};" \
        : "+f"((c)[0]), "+f"((c)[1]), "+f"((c)[2]), "+f"((c)[3]) \
        : "r"((a)[0]), "r"((a)[1]), "r"((a)[2]), "r"((a)[3]), "r"((b)[0]), "r"((b)[1]))

__device__ __forceinline__ uint32_t pack2h(float v0, float v1) {
    __half2 h = __floats2half2_rn(v0, v1);
    return *(uint32_t*)&h;
}

// ---------------------------------------------------------------------------
// mma core: one 64-wide K chunk, warp tile 64 rows x 32 cols, single fp16 term
// smem planes: [rows][64 fp16], 128B/row, SW128 swizzled (validated mapping)
// ---------------------------------------------------------------------------
__device__ __forceinline__ void mma_chunk(float acc[4][4][4],
                                          uint32_t aP, uint32_t bP,
                                          int m0w, int n0w, int lane)
{
    const int lr = lane & 15;
    const int lc = (lane >> 4) << 3;
    const int bi = lane & 7;
    const int bk = ((lane >> 3) & 1) << 3;
#pragma unroll
    for (int ks = 0; ks < 4; ks++) {
        const int k0 = ks * 16;
        uint32_t bf[4][2];
#pragma unroll
        for (int nf = 0; nf < 4; nf++) {
            uint32_t boff = SWZ((uint32_t)((n0w + nf * 8 + bi) * 128 + (k0 + bk) * 2));
            LDSM2(bf[nf], bP + boff);
        }
#pragma unroll
        for (int mf = 0; mf < 4; mf++) {
            uint32_t aoff = SWZ((uint32_t)((m0w + mf * 16 + lr) * 128 + (k0 + lc) * 2));
            uint32_t af[4];
            LDSM4(af, aP + aoff);
#pragma unroll
            for (int nf = 0; nf < 4; nf++)
                MMA16816(acc[mf][nf], af, bf[nf]);
        }
    }
}

// ---------------------------------------------------------------------------
// small kernels
// ---------------------------------------------------------------------------
__global__ void zero_kernel(float* __restrict__ out, int n) {
    int i = blockIdx.x * blockDim.x + threadIdx.x;
    if (i < n) out[i] = 0.f;
}

__global__ void xconv_kernel(const float* __restrict__ x) {
    int i = blockIdx.x * blockDim.x + threadIdx.x;
    if (i < T * H / 2)
        *(uint32_t*)(g_xh + 2 * i) = pack2h(x[2 * i], x[2 * i + 1]);
}

// transpose+convert: in [e][R][C] fp32 -> plane [e][C][R] fp16 (K=R contiguous)
// which: 0 = w_gate, 1 = w_up (R=H,C=M);  2 = w_down (R=M,C=H)
// outputs selected in DEVICE code (host address-of __device__ global is UB).
__global__ void __launch_bounds__(256) trans_kernel(const float* __restrict__ in,
                                                    int which) {
    const int R = (which == 2) ? M : H;
    const int C = (which == 2) ? H : M;
    __half* outp = (which == 0) ? g_wg : (which == 1) ? g_wu : g_wd;

    const int e = blockIdx.z;
    in   += (size_t)e * R * C;
    outp += (size_t)e * R * C;
    const int k0 = blockIdx.x * 64;
    const int n0 = blockIdx.y * 32;
    __shared__ float sm[64][33];
    const int tx = threadIdx.x, ty = threadIdx.y;
#pragma unroll
    for (int i = 0; i < 8; i++)
        sm[ty + i * 8][tx] = in[(size_t)(k0 + ty + i * 8) * C + n0 + tx];
    __syncthreads();
#pragma unroll
    for (int i = 0; i < 4; i++) {
        int n = i * 8 + ty;
        size_t base = (size_t)(n0 + n) * R + k0;
        *(uint32_t*)(outp + base + 2 * tx) = pack2h(sm[2 * tx][n], sm[2 * tx + 1][n]);
    }
}

// ---------------------------------------------------------------------------
// router + grouping (validated; fp32 exact logits)
// ---------------------------------------------------------------------------
__global__ void __launch_bounds__(128) router_kernel(
    const float* __restrict__ x, const float* __restrict__ gw,
    float* __restrict__ logits_out)
{
    const int t = blockIdx.x;
    const int tid = threadIdx.x;
    const float* xr = x + (size_t)t * H;
    float acc[E];
#pragma unroll
    for (int e = 0; e < E; e++) acc[e] = 0.f;
    for (int h = tid; h < H; h += 128) {
        float xv = xr[h];
        const float* g = gw + (size_t)h * E;
#pragma unroll
        for (int e = 0; e < E; e++) acc[e] += xv * g[e];
    }
    __shared__ float red[128][E];
#pragma unroll
    for (int e = 0; e < E; e++) red[tid][e] = acc[e];
    __syncthreads();
    for (int s = 64; s > 0; s >>= 1) {
        if (tid < s)
#pragma unroll
            for (int e = 0; e < E; e++) red[tid][e] += red[tid + s][e];
        __syncthreads();
    }
    if (tid == 0) {
        float l[E];
#pragma unroll
        for (int e = 0; e < E; e++) {
            l[e] = red[0][e];
            if (logits_out) logits_out[(size_t)t * E + e] = l[e];
        }
        float mx = l[0];
#pragma unroll
        for (int e = 1; e < E; e++) mx = fmaxf(mx, l[e]);
        float p[E];
#pragma unroll
        for (int e = 0; e < E; e++) p[e] = expf(l[e] - mx);
        int i0 = 0;
#pragma unroll
        for (int e = 1; e < E; e++) if (p[e] > p[i0]) i0 = e;
        int i1 = (i0 == 0) ? 1 : 0;
#pragma unroll
        for (int e = 0; e < E; e++) if (e != i0 && p[e] > p[i1]) i1 = e;
        float s2 = p[i0] + p[i1];
        g_top_i[t * 2 + 0] = i0; g_top_w[t * 2 + 0] = p[i0] / s2;
        g_top_i[t * 2 + 1] = i1; g_top_w[t * 2 + 1] = p[i1] / s2;
    }
}

__global__ void __launch_bounds__(256) build_assign_kernel() {
    __shared__ int cnt[E], cur[E];
    const int tid = threadIdx.x;
    if (tid < E) cnt[tid] = 0;
    __syncthreads();
    for (int a = tid; a < A_MAX; a += 256) atomicAdd(&cnt[g_top_i[a]], 1);
    __syncthreads();
    if (tid == 0) {
        int o = 0;
        for (int e = 0; e < E; e++) {
            g_expert_count[e] = cnt[e];
            g_expert_offset[e] = o;
            cur[e] = o;
            o += cnt[e];
        }
    }
    __syncthreads();
    for (int a = tid; a < A_MAX; a += 256) {
        int e = g_top_i[a];
        int pos = atomicAdd(&cur[e], 1);
        g_assign_token[pos] = a >> 1;
        g_assign_w[pos]     = g_top_w[a];
    }
}

// ---------------------------------------------------------------------------
// GEMM1: hidden = silu(X*Wg) * (X*Wu)
// 128 gathered rows x 64 cols; warps 0-3 gate, 4-7 up; cp.async double-buffer
// stage (32KB): A 0..16K | BG 16K..24K | BU 24K..32K
// ---------------------------------------------------------------------------
#define G1_STAGE 32768
#define G1_BG 16384
#define G1_BU 24576
#define G1_SROW (2 * G1_STAGE)
#define G1_SMEM (2 * G1_STAGE + 512)

__device__ __forceinline__ void g1_load(uint32_t stg, int e, int n0, int kg,
                                        const int* srow, int tid) {
#pragma unroll
    for (int it = 0; it < 4; it++) {          // A: 128 rows x 128B
        int idx = tid + it * 256;
        int r = idx >> 3, q = idx & 7;
        int tok = srow[r];
        uint32_t sz = (tok >= 0) ? 16u : 0u;
        int tk = (tok >= 0) ? tok : 0;
        uint32_t o = SWZ((uint32_t)(r * 128 + q * 16));
        CP16Z(stg + o, g_xh + (size_t)tk * H + kg + q * 8, sz);
    }
#pragma unroll
    for (int it = 0; it < 2; it++) {          // Bg, Bu: 64 rows x 128B each
        int idx = tid + it * 256;
        int r = idx >> 3, q = idx & 7;
        size_t go = ((size_t)e * M + n0 + r) * H + kg + q * 8;
        uint32_t o = SWZ((uint32_t)(r * 128 + q * 16));
        CP16(stg + G1_BG + o, g_wg + go);
        CP16(stg + G1_BU + o, g_wu + go);
    }
}

__global__ void __launch_bounds__(256, 2) gemm1_mma() {
    const int e   = blockIdx.z;
    const int cnt = g_expert_count[e];
    const int t0  = blockIdx.x * 128;
    if (t0 >= cnt) return;
    const int off = g_expert_offset[e];
    const int n0  = blockIdx.y * 64;

    extern __shared__ __align__(1024) char smem[];
    const uint32_t sb = smem_u32(smem);
    int* srow = (int*)(smem + G1_SROW);
    const int tid = threadIdx.x, wid = tid >> 5, lane = tid & 31;

    if (tid < 128)
        srow[tid] = (t0 + tid < cnt) ? g_assign_token[off + t0 + tid] : -1;
    __syncthreads();

    const int gwp    = wid & 3;
    const int warp_m = gwp >> 1, warp_n = gwp & 1;
    const bool isUp  = wid >= 4;

    float acc[4][4][4];
#pragma unroll
    for (int a = 0; a < 4; a++)
#pragma unroll
        for (int b = 0; b < 4; b++)
#pragma unroll
            for (int c = 0; c < 4; c++) acc[a][b][c] = 0.f;

    const uint32_t bOff = isUp ? G1_BU : G1_BG;

    const int NCH = H / 64;   // 16
    g1_load(sb, e, n0, 0, srow, tid);
    CP_COMMIT();
    for (int ch = 0; ch < NCH; ch++) {
        const uint32_t cur = sb + (uint32_t)(ch & 1) * G1_STAGE;
        if (ch + 1 < NCH) {
            g1_load(sb + (uint32_t)((ch + 1) & 1) * G1_STAGE, e, n0, (ch + 1) * 64, srow, tid);
            CP_COMMIT();
            CP_WAIT(1);
        } else {
            CP_WAIT(0);
        }
        __syncthreads();
        mma_chunk(acc, cur, cur + bOff, warp_m * 64, warp_n * 32, lane);
        __syncthreads();
    }

    // epilogue: exchange up accums via smem, gate warps compute + store fp16
    float* smemU = (float*)smem;   // [128][65] fp32 overlay (33 KB < 64 KB)
    if (isUp) {
#pragma unroll
        for (int mf = 0; mf < 4; mf++)
#pragma unroll
            for (int nf = 0; nf < 4; nf++)
#pragma unroll
                for (int i = 0; i < 4; i++) {
                    int r = warp_m * 64 + mf * 16 + (lane >> 2) + ((i >> 1) << 3);
                    int c = warp_n * 32 + nf * 8 + 2 * (lane & 3) + (i & 1);
                    smemU[r * 65 + c] = acc[mf][nf][i];
                }
    }
    __syncthreads();
    if (!isUp) {
#pragma unroll
        for (int mf = 0; mf < 4; mf++)
#pragma unroll
            for (int nf = 0; nf < 4; nf++) {
                int rb = warp_m * 64 + mf * 16 + (lane >> 2);
                int cb = warp_n * 32 + nf * 8 + 2 * (lane & 3);
#pragma unroll
                for (int hf = 0; hf < 2; hf++) {
                    int r = rb + hf * 8;
                    if (t0 + r < cnt) {
                        float g0 = acc[mf][nf][hf * 2 + 0];
                        float g1 = acc[mf][nf][hf * 2 + 1];
                        float u0 = smemU[r * 65 + cb];
                        float u1 = smemU[r * 65 + cb + 1];
                        float h0 = (g0 / (1.f + __expf(-g0))) * u0;
                        float h1 = (g1 / (1.f + __expf(-g1))) * u1;
                        *(uint32_t*)(g_hid + (size_t)(off + t0 + r) * M + n0 + cb)
                            = pack2h(h0, h1);
                    }
                }
            }
    }
}

// ---------------------------------------------------------------------------
// GEMM2: out += w * (hidden * WdT)
// 128 rows x 128 H-cols; 8 warps (2m x 4n); cp.async double-buffer
// stage (32KB): A 0..16K | BD 16K..32K
// ---------------------------------------------------------------------------
#define G2_STAGE 32768
#define G2_BD 16384
#define G2_SMEM (2 * G2_STAGE)

__device__ __forceinline__ void g2_load(uint32_t stg, int e, int h0, int kg,
                                        int arow0, int tid) {
#pragma unroll
    for (int it = 0; it < 4; it++) {
        int idx = tid + it * 256;
        int r = idx >> 3, q = idx & 7;
        uint32_t o = SWZ((uint32_t)(r * 128 + q * 16));
        CP16(stg + o, g_hid + (size_t)(arow0 + r) * M + kg + q * 8);
    }
#pragma unroll
    for (int it = 0; it < 4; it++) {
        int idx = tid + it * 256;
        int r = idx >> 3, q = idx & 7;
        uint32_t o = SWZ((uint32_t)(r * 128 + q * 16));
        CP16(stg + G2_BD + o, g_wd + ((size_t)e * H + h0 + r) * M + kg + q * 8);
    }
}

__global__ void __launch_bounds__(256, 2) gemm2_mma(float* __restrict__ out) {
    const int e   = blockIdx.z;
    const int cnt = g_expert_count[e];
    const int t0  = blockIdx.x * 128;
    if (t0 >= cnt) return;
    const int off = g_expert_offset[e];
    const int h0  = blockIdx.y * 128;

    extern __shared__ __align__(1024) char smem[];
    const uint32_t sb = smem_u32(smem);
    const int tid = threadIdx.x, wid = tid >> 5, lane = tid & 31;
    const int warp_m = wid >> 2, warp_n = wid & 3;

    float acc[4][4][4];
#pragma unroll
    for (int a = 0; a < 4; a++)
#pragma unroll
        for (int b = 0; b < 4; b++)
#pragma unroll
            for (int c = 0; c < 4; c++) acc[a][b][c] = 0.f;

    const int NCH = M / 64;   // 56
    g2_load(sb, e, h0, 0, off + t0, tid);
    CP_COMMIT();
    for (int ch = 0; ch < NCH; ch++) {
        const uint32_t cur = sb + (uint32_t)(ch & 1) * G2_STAGE;
        if (ch + 1 < NCH) {
            g2_load(sb + (uint32_t)((ch + 1) & 1) * G2_STAGE, e, h0, (ch + 1) * 64, off + t0, tid);
            CP_COMMIT();
            CP_WAIT(1);
        } else {
            CP_WAIT(0);
        }
        __syncthreads();
        mma_chunk(acc, cur, cur + G2_BD, warp_m * 64, warp_n * 32, lane);
        __syncthreads();
    }

    // epilogue: weighted atomic scatter-add
#pragma unroll
    for (int mf = 0; mf < 4; mf++) {
        int rb = warp_m * 64 + mf * 16 + (lane >> 2);
#pragma unroll
        for (int hf = 0; hf < 2; hf++) {
            int r = rb + hf * 8;
            if (t0 + r < cnt) {
                int a = off + t0 + r;
                int tok = g_assign_token[a];
                float w = g_assign_w[a];
                float* orow = out + (size_t)tok * H + h0;
#pragma unroll
                for (int nf = 0; nf < 4; nf++) {
                    int c = warp_n * 32 + nf * 8 + 2 * (lane & 3);
                    atomicAdd(&orow[c],     w * acc[mf][nf][hf * 2 + 0]);
                    atomicAdd(&orow[c + 1], w * acc[mf][nf][hf * 2 + 1]);
                }
            }
        }
    }
}

// ---------------------------------------------------------------------------
// launch
// ---------------------------------------------------------------------------
extern "C" void kernel_launch(void* const* d_in, const int* in_sizes, int n_in,
                              void* d_out, int out_size) {
    const float* hs     = (const float*)d_in[0];
    const float* gate_w = (const float*)d_in[1];
    const float* w_gate = (const float*)d_in[2];
    const float* w_up   = (const float*)d_in[3];
    const float* w_down = (const float*)d_in[4];
    float* out = (float*)d_out;
    float* logits_out = (out_size >= T * H + T * E) ? (out + (size_t)T * H) : nullptr;

    cudaFuncSetAttribute(gemm1_mma, cudaFuncAttributeMaxDynamicSharedMemorySize, G1_SMEM);
    cudaFuncSetAttribute(gemm2_mma, cudaFuncAttributeMaxDynamicSharedMemorySize, G2_SMEM);

    zero_kernel<<<(out_size + 255) / 256, 256>>>(out, out_size);
    xconv_kernel<<<(T * H / 2 + 255) / 256, 256>>>(hs);

    dim3 tb(32, 8);
    trans_kernel<<<dim3(H / 64, M / 32, E), tb>>>(w_gate, 0);
    trans_kernel<<<dim3(H / 64, M / 32, E), tb>>>(w_up,   1);
    trans_kernel<<<dim3(M / 64, H / 32, E), tb>>>(w_down, 2);

    router_kernel<<<T, 128>>>(hs, gate_w, logits_out);
    build_assign_kernel<<<1, 256>>>();

    gemm1_mma<<<dim3(A_MAX / 128, M / 64, E), 256, G1_SMEM>>>();
    gemm2_mma<<<dim3(A_MAX / 128, H / 128, E), 256, G2_SMEM>>>(out);
}